// round 9
// baseline (speedup 1.0000x reference)
#include <cuda_runtime.h>

// 2-layer LSTM (H=100, B=512, L=168) + fc head, 48-step autoregressive rollout.
// 128 CTAs x 4 batch elems; 800 threads = 2 kp-groups x 400 gate rows.
// Thread (g, r) accumulates gate row r over HALF the kp range; partials are
// reduced in the cell-update phase. k processed in PAIRS via fma.rn.f32x2.
//
// Weight pairs g_WP[kp][r] = (WT[2kp][r], WT[2kp+1][r]), WT k-major:
//   kp 0..49   : W_hh0   (layer0 recurrent, input h0)
//   kp 50..99  : W_ih1   (layer1 from h0)
//   kp 100..149: W_hh1   (layer1 recurrent, input h1)
// kp 0..63 resident in smem (204.8 KB); kp 64..149 streamed from L2.
// Group 0: L0 kp 0..24,  L1 kp 50..99  (14 resident + 36 streamed)
// Group 1: L0 kp 25..49, L1 kp 100..149 (50 streamed)
//
// hinT[jp][b][2]: jp 0..49 = h0 pairs, jp 50..99 = h1 pairs; one LDS.128
// broadcast yields the (h_2jp, h_2jp+1) pairs for two batch elements.

#define HH        100
#define R4        400
#define SEQ       168
#define STEPS     48
#define NBC       4
#define NCTA      128
#define NTHREADS  800
#define NSMPAIRS  64
#define NPAIRS    150

__device__ float2 g_WP[NPAIRS * R4];
__device__ float  g_b0[R4], g_b1[R4], g_wx0[R4];
__device__ float  g_fc[HH + 1];

// ---------------------------------------------------------------- prep ----
__device__ __forceinline__ float wt_val(int k, int r,
                                        const float* Whh0, const float* Wih1,
                                        const float* Whh1)
{
    if (k < 100)      return Whh0[r * HH + k];
    else if (k < 200) return Wih1[r * HH + (k - 100)];
    else if (k < 300) return Whh1[r * HH + (k - 200)];
    return 0.f;
}

__global__ void prep_kernel(const float* __restrict__ Wih0,
                            const float* __restrict__ Whh0,
                            const float* __restrict__ bih0,
                            const float* __restrict__ bhh0,
                            const float* __restrict__ Wih1,
                            const float* __restrict__ Whh1,
                            const float* __restrict__ bih1,
                            const float* __restrict__ bhh1,
                            const float* __restrict__ fcw,
                            const float* __restrict__ fcb)
{
    int i0 = blockIdx.x * blockDim.x + threadIdx.x;
    int stride = gridDim.x * blockDim.x;
    for (int idx = i0; idx < NPAIRS * R4; idx += stride) {
        int kp = idx / R4, r = idx - kp * R4;
        g_WP[idx] = make_float2(wt_val(2 * kp,     r, Whh0, Wih1, Whh1),
                                wt_val(2 * kp + 1, r, Whh0, Wih1, Whh1));
    }
    for (int r = i0; r < R4; r += stride) {
        g_b0[r]  = bih0[r] + bhh0[r];
        g_b1[r]  = bih1[r] + bhh1[r];
        g_wx0[r] = Wih0[r];           // IN == 1
    }
    if (i0 < HH)  g_fc[i0] = fcw[i0];
    if (i0 == HH) g_fc[HH] = fcb[0];
}

// ---------------------------------------------------------------- math ----
typedef unsigned long long u64;

__device__ __forceinline__ void ffma2(u64& acc, u64 w, u64 h) {
    asm("fma.rn.f32x2 %0, %1, %2, %0;" : "+l"(acc) : "l"(w), "l"(h));
}
__device__ __forceinline__ float hsum2(u64 v) {
    float lo, hi;
    asm("mov.b64 {%0, %1}, %2;" : "=f"(lo), "=f"(hi) : "l"(v));
    return lo + hi;
}
__device__ __forceinline__ float sigf(float v) {
    return 1.f / (1.f + __expf(-v));
}
__device__ __forceinline__ float tanhfast(float v) {
    return __fdividef(2.f, 1.f + __expf(-2.f * v)) - 1.f;
}

// smem layout (float offsets)
#define SM_WP   0                                  // 64 * 400 * 2 = 51200
#define SM_HT   (NSMPAIRS * R4 * 2)                // hinT: 100 jp * 8 = 800
#define SM_G    (SM_HT + 100 * 8)                  // partial gates: 800*4
#define SM_C0   (SM_G + NTHREADS * 4)              // 400
#define SM_C1   (SM_C0 + R4)                       // 400
#define SM_FC   (SM_C1 + R4)                       // 104
#define SM_XT   (SM_FC + 104)                      // 4
#define SM_Y    (SM_XT + 4)                        // 4
#define SM_TOT  (SM_Y + 4)                         // 56112 f = 224448 B

__global__ void __launch_bounds__(NTHREADS, 1)
lstm_kernel(const float* __restrict__ x, float* __restrict__ out)
{
    extern __shared__ float sm[];
    float2*     sWP  = (float2*)sm;
    float*      sHf  = sm + SM_HT;
    ulonglong2* sHu  = (ulonglong2*)(sm + SM_HT);
    float*      sGf  = sm + SM_G;
    float4*     sG4  = (float4*)sGf;
    float*      sC0  = sm + SM_C0;
    float*      sC1  = sm + SM_C1;
    float*      sFC  = sm + SM_FC;
    float*      sXt  = sm + SM_XT;
    float*      sY   = sm + SM_Y;

    const int tid = threadIdx.x;          // 0..799
    const int g   = tid >= R4;            // kp-group
    const int r   = tid - g * R4;         // gate row 0..399
    const int bb  = blockIdx.x * NBC;

    // resident weight pairs (coalesced), zero state, fc copy
    for (int i = tid; i < NSMPAIRS * R4; i += NTHREADS) sWP[i] = g_WP[i];
    for (int i = tid; i < 100 * 8; i += NTHREADS) sHf[i] = 0.f;
    for (int i = tid; i < R4; i += NTHREADS) { sC0[i] = 0.f; sC1[i] = 0.f; }
    for (int i = tid; i < HH + 1; i += NTHREADS) sFC[i] = g_fc[i];
    if (tid < NBC) sXt[tid] = x[(bb + tid) * SEQ];

    const float wx0 = g_wx0[r];
    const float b0r = g_b0[r];
    const float b1r = g_b1[r];
    const int   jb_b = (tid < R4) ? tid / HH : 0;
    const int   jb_j = (tid < R4) ? tid - jb_b * HH : 0;
    const int   hoff = (jb_j >> 1) * 8 + jb_b * 2 + (jb_j & 1);

    // per-group bases
    const float2* wL0   = sWP + (g ? 25 : 0) * R4 + r;   // 25 resident pairs
    const float2* wL1r  = sWP + 50 * R4 + r;             // g0: kp 50..63
    const float2* wL1s  = g_WP + (g ? 100 : 64) * R4 + r;// streamed base
    const int     jpL0  = g ? 25 : 0;
    const int     nStr  = g ? 50 : 36;
    const int     jpStr = g ? 50 : 14;

    __syncthreads();

    for (int s = 0; s < STEPS; s++) {
        for (int t = 0; t < SEQ; t++) {
            // ================= layer 0 partial gates =================
            u64 c0 = 0, c1 = 0, c2 = 0, c3 = 0;
            #pragma unroll 5
            for (int i = 0; i < 25; i++) {
                u64 w2 = *(const u64*)(wL0 + i * R4);
                ulonglong2 hA = sHu[2 * (jpL0 + i)];
                ulonglong2 hB = sHu[2 * (jpL0 + i) + 1];
                ffma2(c0, w2, hA.x);
                ffma2(c1, w2, hA.y);
                ffma2(c2, w2, hB.x);
                ffma2(c3, w2, hB.y);
            }
            if (!g) {
                float4 xv4 = *(const float4*)sXt;
                sG4[tid] = make_float4(fmaf(wx0, xv4.x, b0r) + hsum2(c0),
                                       fmaf(wx0, xv4.y, b0r) + hsum2(c1),
                                       fmaf(wx0, xv4.z, b0r) + hsum2(c2),
                                       fmaf(wx0, xv4.w, b0r) + hsum2(c3));
            } else {
                sG4[tid] = make_float4(hsum2(c0), hsum2(c1),
                                       hsum2(c2), hsum2(c3));
            }
            __syncthreads();

            // ---- layer 0 cell update (threads 0..399) + x prefetch ----
            if (tid < R4) {
                float gi = sGf[ jb_j       *4+jb_b] + sGf[(R4+jb_j)    *4+jb_b];
                float gf = sGf[(jb_j+100)*4+jb_b] + sGf[(R4+jb_j+100)*4+jb_b];
                float gg = sGf[(jb_j+200)*4+jb_b] + sGf[(R4+jb_j+200)*4+jb_b];
                float go = sGf[(jb_j+300)*4+jb_b] + sGf[(R4+jb_j+300)*4+jb_b];
                float c  = sC0[jb_j * 4 + jb_b];
                float cn = sigf(gf) * c + sigf(gi) * tanhfast(gg);
                float hn = sigf(go) * tanhfast(cn);
                sC0[jb_j * 4 + jb_b] = cn;
                sHf[hoff] = hn;                       // h0 -> hinT jp 0..49
            } else if (tid < R4 + NBC) {
                // prefetch x for next timestep (sY written >=167 steps ago)
                int b  = tid - R4;
                int t2 = (t < SEQ - 1) ? t + 1 : 0;
                int s2 = (t < SEQ - 1) ? s : s + 1;
                if (s2 < STEPS) {
                    float xv;
                    if (s2 == 0)           xv = x[(bb + b) * SEQ + t2];
                    else if (t2 < SEQ - 1) xv = x[(bb + b) * SEQ + t2 + 1];
                    else                   xv = sY[b];
                    sXt[b] = xv;
                }
            }
            __syncthreads();

            // ================= layer 1 partial gates =================
            c0 = 0; c1 = 0; c2 = 0; c3 = 0;
            if (!g) {
                #pragma unroll
                for (int i = 0; i < 14; i++) {        // resident kp 50..63
                    u64 w2 = *(const u64*)(wL1r + i * R4);
                    ulonglong2 hA = sHu[2 * i];
                    ulonglong2 hB = sHu[2 * i + 1];
                    ffma2(c0, w2, hA.x);
                    ffma2(c1, w2, hA.y);
                    ffma2(c2, w2, hB.x);
                    ffma2(c3, w2, hB.y);
                }
            }
            #pragma unroll 6
            for (int i = 0; i < nStr; i++) {          // streamed pairs
                u64 w2 = __ldg((const u64*)(wL1s + i * R4));
                int jp = jpStr + i;
                ulonglong2 hA = sHu[2 * jp];
                ulonglong2 hB = sHu[2 * jp + 1];
                ffma2(c0, w2, hA.x);
                ffma2(c1, w2, hA.y);
                ffma2(c2, w2, hB.x);
                ffma2(c3, w2, hB.y);
            }
            if (!g) {
                sG4[tid] = make_float4(b1r + hsum2(c0), b1r + hsum2(c1),
                                       b1r + hsum2(c2), b1r + hsum2(c3));
            } else {
                sG4[tid] = make_float4(hsum2(c0), hsum2(c1),
                                       hsum2(c2), hsum2(c3));
            }
            __syncthreads();

            // ---- layer 1 cell update (threads 0..399) ----
            if (tid < R4) {
                float gi = sGf[ jb_j       *4+jb_b] + sGf[(R4+jb_j)    *4+jb_b];
                float gf = sGf[(jb_j+100)*4+jb_b] + sGf[(R4+jb_j+100)*4+jb_b];
                float gg = sGf[(jb_j+200)*4+jb_b] + sGf[(R4+jb_j+200)*4+jb_b];
                float go = sGf[(jb_j+300)*4+jb_b] + sGf[(R4+jb_j+300)*4+jb_b];
                float c  = sC1[jb_j * 4 + jb_b];
                float cn = sigf(gf) * c + sigf(gi) * tanhfast(gg);
                float hn = sigf(go) * tanhfast(cn);
                sC1[jb_j * 4 + jb_b] = cn;
                sHf[400 + hoff] = hn;                 // h1 -> hinT jp 50..99
            }
            __syncthreads();

            // ---- fc head at sequence end (overlaps next L0 phase) ----
            if (t == SEQ - 1 && tid < 128) {
                int b = tid >> 5, l = tid & 31;
                float p = 0.f;
                for (int j = l; j < HH; j += 32)
                    p += sHf[400 + (j >> 1) * 8 + b * 2 + (j & 1)] * sFC[j];
                #pragma unroll
                for (int off = 16; off; off >>= 1)
                    p += __shfl_down_sync(0xffffffffu, p, off);
                if (l == 0) {
                    float y = p + sFC[HH];
                    sY[b] = y;                         // next reader 167 steps away
                    out[(bb + b) * STEPS + s] = y;
                }
            }
        }
    }
}

// -------------------------------------------------------------- launch ----
extern "C" void kernel_launch(void* const* d_in, const int* in_sizes, int n_in,
                              void* d_out, int out_size)
{
    const float* x    = (const float*)d_in[0];
    const float* Wih0 = (const float*)d_in[1];
    const float* Whh0 = (const float*)d_in[2];
    const float* bih0 = (const float*)d_in[3];
    const float* bhh0 = (const float*)d_in[4];
    const float* Wih1 = (const float*)d_in[5];
    const float* Whh1 = (const float*)d_in[6];
    const float* bih1 = (const float*)d_in[7];
    const float* bhh1 = (const float*)d_in[8];
    const float* fcw  = (const float*)d_in[9];
    const float* fcb  = (const float*)d_in[10];
    float* out = (float*)d_out;

    cudaFuncSetAttribute(lstm_kernel,
                         cudaFuncAttributeMaxDynamicSharedMemorySize,
                         SM_TOT * (int)sizeof(float));

    prep_kernel<<<128, 256>>>(Wih0, Whh0, bih0, bhh0,
                              Wih1, Whh1, bih1, bhh1, fcw, fcb);
    lstm_kernel<<<NCTA, NTHREADS, SM_TOT * (int)sizeof(float)>>>(x, out);
}

// round 10
// speedup vs baseline: 1.1824x; 1.1824x over previous
#include <cuda_runtime.h>

// 2-layer LSTM (H=100, B=512, L=168) + fc head, 48-step autoregressive rollout.
// LAYER-PIPELINED: group L0 (threads 0..415) computes layer0 at time u while
// group L1 (threads 416..831) computes layer1 at time u-1 (they are data-
// independent: L0(u) needs h0(u-1); L1(u-1) needs h0(u-1), h1(u-2)).
// 128 CTAs x 4 batch elems. 400 active rows per group (gate order i,f,g,o).
//
// Weights packed as QUADS g_WQ[q][r] = (w[4q][r], w[4q+1][r], w[4q+2][r],
// w[4q+3][r]) with w k-major over the concatenated k-range:
//   k 0..99   = W_hh0 (layer0)          -> quads 0..24
//   k 100..199= W_ih1 (layer1, from h0) -> quads 25..49
//   k 200..299= W_hh1 (layer1, from h1) -> quads 50..74
// Quads 0..29 resident in smem (192 KB); quads 30..74 streamed from L2.
// Group L0: gates0 = quads 0..24 ; partial gates1 = quads 25..37 (5 res + 8 str)
// Group L1: partial gates1 = quads 38..74 (37 streamed)
// gates1 = partialA + partialB (reduced in the cell-1 phase).
//
// hT[jp][b][2]: jp 0..49 = h0 k-pairs, jp 50..99 = h1 k-pairs; one LDS.128
// broadcast yields the (h_2jp, h_2jp+1) pairs for two batch elements.
// fma.rn.f32x2 accumulates both k's of a pair per instruction (pure fp32).

#define HH        100
#define R4        400
#define SEQ       168
#define STEPS     48
#define NBC       4
#define NCTA      128
#define NTHREADS  832
#define GRP1      416
#define NQRES     30          // resident quads
#define NQUADS    75

__device__ float4 g_WQ[NQUADS * R4];
__device__ float  g_b0[R4], g_b1[R4], g_wx0[R4];
__device__ float  g_fc[HH + 1];

// ---------------------------------------------------------------- prep ----
__device__ __forceinline__ float wt_val(int k, int r,
                                        const float* Whh0, const float* Wih1,
                                        const float* Whh1)
{
    if (k < 100)      return Whh0[r * HH + k];
    else if (k < 200) return Wih1[r * HH + (k - 100)];
    else              return Whh1[r * HH + (k - 200)];
}

__global__ void prep_kernel(const float* __restrict__ Wih0,
                            const float* __restrict__ Whh0,
                            const float* __restrict__ bih0,
                            const float* __restrict__ bhh0,
                            const float* __restrict__ Wih1,
                            const float* __restrict__ Whh1,
                            const float* __restrict__ bih1,
                            const float* __restrict__ bhh1,
                            const float* __restrict__ fcw,
                            const float* __restrict__ fcb)
{
    int i0 = blockIdx.x * blockDim.x + threadIdx.x;
    int stride = gridDim.x * blockDim.x;
    for (int idx = i0; idx < NQUADS * R4; idx += stride) {
        int q = idx / R4, r = idx - q * R4;
        g_WQ[idx] = make_float4(wt_val(4*q,   r, Whh0, Wih1, Whh1),
                                wt_val(4*q+1, r, Whh0, Wih1, Whh1),
                                wt_val(4*q+2, r, Whh0, Wih1, Whh1),
                                wt_val(4*q+3, r, Whh0, Wih1, Whh1));
    }
    for (int r = i0; r < R4; r += stride) {
        g_b0[r]  = bih0[r] + bhh0[r];
        g_b1[r]  = bih1[r] + bhh1[r];
        g_wx0[r] = Wih0[r];           // IN == 1
    }
    if (i0 < HH)  g_fc[i0] = fcw[i0];
    if (i0 == HH) g_fc[HH] = fcb[0];
}

// ---------------------------------------------------------------- math ----
typedef unsigned long long u64;

__device__ __forceinline__ void ffma2(u64& acc, u64 w, u64 h) {
    asm("fma.rn.f32x2 %0, %1, %2, %0;" : "+l"(acc) : "l"(w), "l"(h));
}
__device__ __forceinline__ float hsum2(u64 v) {
    float lo, hi;
    asm("mov.b64 {%0, %1}, %2;" : "=f"(lo), "=f"(hi) : "l"(v));
    return lo + hi;
}
__device__ __forceinline__ float sigf(float v) {
    return 1.f / (1.f + __expf(-v));
}
__device__ __forceinline__ float tanhfast(float v) {
    return __fdividef(2.f, 1.f + __expf(-2.f * v)) - 1.f;
}

// one quad: 2 pair-weights (w.x = pair 2q, w.y = pair 2q+1), h base hb
#define QUAD(wv, hb)                                                      \
    do {                                                                  \
        ulonglong2 hA0 = sHu[(hb)];     ulonglong2 hB0 = sHu[(hb) + 1];   \
        ulonglong2 hA1 = sHu[(hb) + 2]; ulonglong2 hB1 = sHu[(hb) + 3];   \
        ffma2(c0, (wv).x, hA0.x); ffma2(c1, (wv).x, hA0.y);               \
        ffma2(c2, (wv).x, hB0.x); ffma2(c3, (wv).x, hB0.y);               \
        ffma2(c0, (wv).y, hA1.x); ffma2(c1, (wv).y, hA1.y);               \
        ffma2(c2, (wv).y, hB1.x); ffma2(c3, (wv).y, hB1.y);               \
    } while (0)

// smem layout (float offsets)
#define SM_WQ   0                              // 30*400*4 = 48000
#define SM_HT   (NQRES * R4 * 4)               // 800 (100 jp * 8)
#define SM_G0   (SM_HT + 800)                  // 1600
#define SM_G1A  (SM_G0 + 1600)                 // 1600
#define SM_G1B  (SM_G1A + 1600)                // 1600
#define SM_C0   (SM_G1B + 1600)                // 400
#define SM_C1   (SM_C0 + R4)                   // 400
#define SM_FC   (SM_C1 + R4)                   // 104
#define SM_XT   (SM_FC + 104)                  // 4
#define SM_Y    (SM_XT + 4)                    // 4
#define SM_TOT  (SM_Y + 4)                     // 54512 f = 218048 B

__global__ void __launch_bounds__(NTHREADS, 1)
lstm_kernel(const float* __restrict__ x, float* __restrict__ out)
{
    extern __shared__ float sm[];
    ulonglong2* sWQ = (ulonglong2*)sm;             // quad view: [q*400 + r]
    float*      sHf = sm + SM_HT;
    ulonglong2* sHu = (ulonglong2*)(sm + SM_HT);   // [2*jp + (bpair)]
    float*      sG0 = sm + SM_G0;
    float*      sG1A = sm + SM_G1A;
    float*      sG1B = sm + SM_G1B;
    float*      sC0 = sm + SM_C0;
    float*      sC1 = sm + SM_C1;
    float*      sFC = sm + SM_FC;
    float*      sXt = sm + SM_XT;
    float*      sY  = sm + SM_Y;

    const int tid  = threadIdx.x;                  // 0..831
    const int gl1  = tid >= GRP1;                  // group flag
    const int r    = gl1 ? tid - GRP1 : tid;       // row within group
    const bool act = r < R4;
    const bool aL0 = !gl1 && act;
    const bool aL1 =  gl1 && act;
    const int bb   = blockIdx.x * NBC;

    // resident quads (coalesced), zero state, fc copy
    {
        const float4* src = g_WQ;
        float4*       dst = (float4*)sm;
        for (int i = tid; i < NQRES * R4; i += NTHREADS) dst[i] = src[i];
    }
    for (int i = tid; i < 800; i += NTHREADS) sHf[i] = 0.f;
    for (int i = tid; i < R4; i += NTHREADS) { sC0[i] = 0.f; sC1[i] = 0.f; }
    for (int i = tid; i < HH + 1; i += NTHREADS) sFC[i] = g_fc[i];
    if (tid < NBC) sXt[tid] = x[(bb + tid) * SEQ];

    const int   rr   = act ? r : 0;
    const float wx0  = g_wx0[rr];
    const float b0r  = g_b0[rr];
    const float b1r  = g_b1[rr];
    const int   jb_b = rr / HH;
    const int   jb_j = rr - jb_b * HH;
    const int   hoff = (jb_j >> 1) * 8 + jb_b * 2 + (jb_j & 1);

    // weight bases
    const ulonglong2* w00 = sWQ + rr;                            // quads 0..24
    const ulonglong2* w1r = sWQ + 25 * R4 + rr;                  // quads 25..29
    const ulonglong2* w1sA = (const ulonglong2*)g_WQ + 30 * R4 + rr; // 30..37
    const ulonglong2* w1sB = (const ulonglong2*)g_WQ + 38 * R4 + rr; // 38..74

    __syncthreads();

    for (int s = 0; s < STEPS; s++) {
        for (int u = 0; u <= SEQ; u++) {
            // ===================== phase 1: gates =====================
            if (aL0) {
                if (u < SEQ) {
                    // gates0(u): quads 0..24 over h0(u-1)
                    u64 c0, c1, c2, c3;
                    {
                        float4 xv4 = *(const float4*)sXt;
                        float i0 = fmaf(wx0, xv4.x, b0r);
                        float i1 = fmaf(wx0, xv4.y, b0r);
                        float i2 = fmaf(wx0, xv4.z, b0r);
                        float i3 = fmaf(wx0, xv4.w, b0r);
                        asm("mov.b64 %0, {%1, %2};" : "=l"(c0) : "f"(i0), "f"(0.f));
                        asm("mov.b64 %0, {%1, %2};" : "=l"(c1) : "f"(i1), "f"(0.f));
                        asm("mov.b64 %0, {%1, %2};" : "=l"(c2) : "f"(i2), "f"(0.f));
                        asm("mov.b64 %0, {%1, %2};" : "=l"(c3) : "f"(i3), "f"(0.f));
                    }
                    #pragma unroll 5
                    for (int q = 0; q < 25; q++) {
                        ulonglong2 w = w00[q * R4];
                        QUAD(w, 4 * q);
                    }
                    ((float4*)sG0)[r] = make_float4(hsum2(c0), hsum2(c1),
                                                    hsum2(c2), hsum2(c3));
                }
                if (u >= 1) {
                    // partial gates1(u-1): quads 25..37 (h0 jp 0..25)
                    u64 c0 = 0, c1 = 0, c2 = 0, c3 = 0;
                    #pragma unroll
                    for (int q = 0; q < 5; q++) {          // resident 25..29
                        ulonglong2 w = w1r[q * R4];
                        QUAD(w, 4 * q);
                    }
                    #pragma unroll
                    for (int q = 0; q < 8; q++) {          // streamed 30..37
                        ulonglong2 w = __ldg(w1sA + q * R4);
                        QUAD(w, 20 + 4 * q);
                    }
                    ((float4*)sG1A)[r] = make_float4(hsum2(c0), hsum2(c1),
                                                     hsum2(c2), hsum2(c3));
                }
            }
            if (aL1 && u >= 1) {
                // partial gates1(u-1): quads 38..74 (h0 jp 26..49, h1 jp 50..99)
                u64 c0 = 0, c1 = 0, c2 = 0, c3 = 0;
                #pragma unroll 4
                for (int q = 0; q < 37; q++) {
                    ulonglong2 w = __ldg(w1sB + q * R4);
                    QUAD(w, 52 + 4 * q);
                }
                ((float4*)sG1B)[r] = make_float4(b1r + hsum2(c0), b1r + hsum2(c1),
                                                 b1r + hsum2(c2), b1r + hsum2(c3));
            }
            __syncthreads();

            // ===================== phase 2: cells =====================
            if (aL0 && u < SEQ) {
                int o = jb_j * 4 + jb_b;
                float gi = sG0[o];
                float gf = sG0[(jb_j + 100) * 4 + jb_b];
                float gg = sG0[(jb_j + 200) * 4 + jb_b];
                float go = sG0[(jb_j + 300) * 4 + jb_b];
                float c  = sC0[o];
                float cn = sigf(gf) * c + sigf(gi) * tanhfast(gg);
                float hn = sigf(go) * tanhfast(cn);
                sC0[o]    = cn;
                sHf[hoff] = hn;                        // h0(u)
            }
            if (aL1 && u >= 1) {
                int o = jb_j * 4 + jb_b;
                float gi = sG1A[o] + sG1B[o];
                float gf = sG1A[(jb_j+100)*4+jb_b] + sG1B[(jb_j+100)*4+jb_b];
                float gg = sG1A[(jb_j+200)*4+jb_b] + sG1B[(jb_j+200)*4+jb_b];
                float go = sG1A[(jb_j+300)*4+jb_b] + sG1B[(jb_j+300)*4+jb_b];
                float c  = sC1[o];
                float cn = sigf(gf) * c + sigf(gi) * tanhfast(gg);
                float hn = sigf(go) * tanhfast(cn);
                sC1[o]          = cn;
                sHf[400 + hoff] = hn;                  // h1(u-1)
            }
            if (tid >= GRP1 + 400 && tid < GRP1 + 404 && u < SEQ) {
                // prefetch x for next iteration (idle L1 lanes)
                int b = tid - (GRP1 + 400);
                float xv;
                if (u < SEQ - 1) {
                    int tt = u + 1;
                    if (s == 0)           xv = x[(bb + b) * SEQ + tt];
                    else if (tt < SEQ-1)  xv = x[(bb + b) * SEQ + tt + 1];
                    else                  xv = sY[b];   // y(s-1), stable
                } else {
                    // u == SEQ-1: x(0) of seq s+1 (s+1 >= 1)
                    xv = x[(bb + b) * SEQ + 1];
                }
                sXt[b] = xv;
            }
            __syncthreads();
        }

        // ---- fc head: y(s) from h1(SEQ-1) (threads 0..127, L0 group) ----
        if (tid < 128) {
            int b = tid >> 5, l = tid & 31;
            float p = 0.f;
            for (int j = l; j < HH; j += 32)
                p += sHf[400 + (j >> 1) * 8 + b * 2 + (j & 1)] * sFC[j];
            #pragma unroll
            for (int off = 16; off; off >>= 1)
                p += __shfl_down_sync(0xffffffffu, p, off);
            if (l == 0) {
                float y = p + sFC[HH];
                sY[b] = y;                 // read at u=SEQ-2 of seq s+1
                out[(bb + b) * STEPS + s] = y;
            }
        }
        // no sync needed: h1 is next written at phase2 of u=1 (after 2 syncs),
        // and fc threads rejoin at the phase-1 sync of u=0.
    }
}

// -------------------------------------------------------------- launch ----
extern "C" void kernel_launch(void* const* d_in, const int* in_sizes, int n_in,
                              void* d_out, int out_size)
{
    const float* x    = (const float*)d_in[0];
    const float* Wih0 = (const float*)d_in[1];
    const float* Whh0 = (const float*)d_in[2];
    const float* bih0 = (const float*)d_in[3];
    const float* bhh0 = (const float*)d_in[4];
    const float* Wih1 = (const float*)d_in[5];
    const float* Whh1 = (const float*)d_in[6];
    const float* bih1 = (const float*)d_in[7];
    const float* bhh1 = (const float*)d_in[8];
    const float* fcw  = (const float*)d_in[9];
    const float* fcb  = (const float*)d_in[10];
    float* out = (float*)d_out;

    cudaFuncSetAttribute(lstm_kernel,
                         cudaFuncAttributeMaxDynamicSharedMemorySize,
                         SM_TOT * (int)sizeof(float));

    prep_kernel<<<128, 256>>>(Wih0, Whh0, bih0, bhh0,
                              Wih1, Whh1, bih1, bhh1, fcw, fcb);
    lstm_kernel<<<NCTA, NTHREADS, SM_TOT * (int)sizeof(float)>>>(x, out);
}